// round 3
// baseline (speedup 1.0000x reference)
#include <cuda_runtime.h>

#define BATCH  64
#define WIDTH  64
#define NPTS   8192
#define MODES  16
#define NROWS  (BATCH*WIDTH)          // 4096
#define HSIZE  (NROWS*NPTS)           // 33,554,432 floats (128 MB)
#define KSPLIT 8

// ---------------- device scratch (allocation-free rule: __device__ globals) ----------------
__device__ float g_hA[HSIZE];
__device__ float g_hB[HSIZE];
__device__ float g_cos[MODES*NPTS];
__device__ float g_sin[MODES*NPTS];
__device__ float g_Fp[KSPLIT*NROWS*32];   // forward-DFT partials
__device__ float g_F[NROWS*32];           // [row][0..15]=sum h*cos, [16..31]=sum h*sin
__device__ float g_G[BATCH*2*MODES*WIDTH];// [b][re/im][k][o], pre-scaled by (k==0?1:2)/N

// ---------------- f32x2 packed helpers ----------------
__device__ __forceinline__ unsigned long long ff2(unsigned long long a, unsigned long long b,
                                                  unsigned long long c) {
    unsigned long long d;
    asm("fma.rn.f32x2 %0, %1, %2, %3;" : "=l"(d) : "l"(a), "l"(b), "l"(c));
    return d;
}
__device__ __forceinline__ unsigned long long dup2(float x) {
    unsigned long long r;
    asm("mov.b64 %0, {%1, %2};" : "=l"(r) : "f"(x), "f"(x));
    return r;
}
__device__ __forceinline__ float2 unp2(unsigned long long v) {
    float2 r;
    asm("mov.b64 {%0, %1}, %2;" : "=f"(r.x), "=f"(r.y) : "l"(v));
    return r;
}
__device__ __forceinline__ float gelu_exact(float v) {
    return 0.5f * v * (1.0f + erff(v * 0.7071067811865476f));
}

// ---------------- basis tables: cos/sin(2*pi*k*n/N) ----------------
__global__ void k_basis() {
    int idx = blockIdx.x * blockDim.x + threadIdx.x;
    if (idx >= MODES * NPTS) return;
    int k = idx >> 13, n = idx & (NPTS - 1);
    int r = (k * n) & (NPTS - 1);
    float a = (float)r * (1.0f / 4096.0f);   // angle = pi * a
    float s, c;
    sincospif(a, &s, &c);
    g_cos[idx] = c;
    g_sin[idx] = s;
}

// ---------------- lifting: h = x*pw[w][0] + grid*pw[w][1] + pb[w] ----------------
__global__ void k_lift(const float* __restrict__ x, const float* __restrict__ pw,
                       const float* __restrict__ pb) {
    int idx = blockIdx.x * blockDim.x + threadIdx.x;   // < HSIZE
    int b = idx >> 19;            // /(64*8192)
    int w = (idx >> 13) & 63;
    int n = idx & (NPTS - 1);
    float xv = x[(b << 13) | n];
    float gr = (float)n * (1.0f / 8191.0f);
    g_hA[idx] = xv * pw[2 * w] + gr * pw[2 * w + 1] + pb[w];
}

// ---------------- forward DFT: block = 128 rows x 32 cols, K-chunk 1024 ----------------
__global__ void __launch_bounds__(128) k_fwd(const float* __restrict__ h) {
    __shared__ float hs[128][33];
    __shared__ float bs[32][33];
    const int tid = threadIdx.x;
    const int rt = tid >> 3;            // 0..15 (rows)
    const int ct = tid & 7;             // 0..7  (col groups of 4)
    const int rowBase = blockIdx.x * 128;
    const int n0 = blockIdx.y * 1024;

    float acc[8][4];
#pragma unroll
    for (int j = 0; j < 8; j++)
#pragma unroll
        for (int c = 0; c < 4; c++) acc[j][c] = 0.0f;

    for (int kt = 0; kt < 32; kt++) {
        const int nb = n0 + kt * 32;
        // stage h tile [128 rows x 32 k]
#pragma unroll
        for (int t = 0; t < 8; t++) {
            int f4 = tid + t * 128;
            int row = f4 >> 3, c4 = (f4 & 7) << 2;
            float4 v = *reinterpret_cast<const float4*>(h + (size_t)(rowBase + row) * NPTS + nb + c4);
            hs[row][c4] = v.x; hs[row][c4 + 1] = v.y; hs[row][c4 + 2] = v.z; hs[row][c4 + 3] = v.w;
        }
        // stage basis tile [32 k x 32 cols] (cols: 16 cos then 16 sin)
#pragma unroll
        for (int t = 0; t < 8; t++) {
            int e = tid + t * 128;
            int kk = e & 31, c = e >> 5;
            float v = (c < 16) ? g_cos[c * NPTS + nb + kk] : g_sin[(c - 16) * NPTS + nb + kk];
            bs[kk][c] = v;
        }
        __syncthreads();
#pragma unroll
        for (int kk = 0; kk < 32; kk++) {
            float a[8], bb[4];
#pragma unroll
            for (int j = 0; j < 8; j++) a[j] = hs[rt * 8 + j][kk];
#pragma unroll
            for (int c = 0; c < 4; c++) bb[c] = bs[kk][ct * 4 + c];
#pragma unroll
            for (int j = 0; j < 8; j++)
#pragma unroll
                for (int c = 0; c < 4; c++) acc[j][c] += a[j] * bb[c];
        }
        __syncthreads();
    }
    float* dst = g_Fp + (size_t)blockIdx.y * (NROWS * 32);
#pragma unroll
    for (int j = 0; j < 8; j++)
#pragma unroll
        for (int c = 0; c < 4; c++)
            dst[(rowBase + rt * 8 + j) * 32 + ct * 4 + c] = acc[j][c];
}

__global__ void k_fred() {
    int idx = blockIdx.x * blockDim.x + threadIdx.x;   // < NROWS*32
    float s = 0.0f;
#pragma unroll
    for (int p = 0; p < KSPLIT; p++) s += g_Fp[p * (NROWS * 32) + idx];
    g_F[idx] = s;
}

// ---------------- mode mix: G[b][o][k] = sum_i F[b][i][k] * W[i][o][k] (complex), scaled ----------------
__global__ void k_mix(const float* __restrict__ wr, const float* __restrict__ wi) {
    __shared__ float Fs[64][32];
    const int b = blockIdx.x, tid = threadIdx.x;
#pragma unroll
    for (int t = 0; t < 8; t++) {
        int e = tid + t * 256;
        Fs[e >> 5][e & 31] = g_F[b * 2048 + e];
    }
    __syncthreads();
    const int k = tid & 15, og = tid >> 4;   // og 0..15
#pragma unroll
    for (int rep = 0; rep < 4; rep++) {
        int o = og + rep * 16;
        float gre = 0.0f, gim = 0.0f;
#pragma unroll 8
        for (int i = 0; i < 64; i++) {
            float fr = Fs[i][k];
            float S  = Fs[i][16 + k];        // S = sum h*sin, so Fim = -S
            float wrv = wr[(i * 64 + o) * 16 + k];
            float wiv = wi[(i * 64 + o) * 16 + k];
            gre += fr * wrv + S * wiv;       // Fre*Wr - Fim*Wi
            gim += fr * wiv - S * wrv;       // Fre*Wi + Fim*Wr
        }
        float sc = (k == 0 ? 1.0f : 2.0f) * (1.0f / (float)NPTS);
        g_G[(b * 2 + 0) * 1024 + k * 64 + o] = gre * sc;
        g_G[(b * 2 + 1) * 1024 + k * 64 + o] = gim * sc;
    }
}

// ---------------- fused: x1 (inverse basis) + x2 (pointwise) + bias + GELU ----------------
#define SM_LAYER_FLOATS (64*132 + 64*64 + 16*128 + 16*128 + 16*64 + 16*64)
__global__ void __launch_bounds__(128) k_layer(const float* __restrict__ h,
                                               float* __restrict__ out,
                                               const float* __restrict__ ww,
                                               const float* __restrict__ wb) {
    extern __shared__ float sm[];
    float* hs = sm;                 // [64][132]
    float* Ws = hs + 64 * 132;      // [o][i] 64x64
    float* cs = Ws + 4096;          // [16][128]
    float* sn = cs + 2048;          // [16][128]
    float* Gr = sn + 2048;          // [16][64]
    float* Gi = Gr + 1024;          // [16][64]

    const int b = blockIdx.y;
    const int n0 = blockIdx.x * 128;
    const int tid = threadIdx.x;
    const int ot = tid >> 4;        // 0..7
    const int nt = tid & 15;        // 0..15

    // stage h tile [64 i][128 n]
#pragma unroll
    for (int t = 0; t < 16; t++) {
        int f4 = tid + t * 128;
        int row = f4 >> 5, c4 = (f4 & 31) << 2;
        float4 v = *reinterpret_cast<const float4*>(h + (size_t)(b * 64 + row) * NPTS + n0 + c4);
        *reinterpret_cast<float4*>(hs + row * 132 + c4) = v;
    }
    // stage W [o][i]
#pragma unroll
    for (int t = 0; t < 8; t++) {
        int e = (tid + t * 128) * 4;
        *reinterpret_cast<float4*>(Ws + e) = *reinterpret_cast<const float4*>(ww + e);
    }
    // stage basis tiles
#pragma unroll
    for (int t = 0; t < 4; t++) {
        int e = (tid + t * 128) * 4;
        int k2 = e >> 7, nn = e & 127;
        *reinterpret_cast<float4*>(cs + e) = *reinterpret_cast<const float4*>(g_cos + k2 * NPTS + n0 + nn);
        *reinterpret_cast<float4*>(sn + e) = *reinterpret_cast<const float4*>(g_sin + k2 * NPTS + n0 + nn);
    }
    // stage G
#pragma unroll
    for (int t = 0; t < 2; t++) {
        int e = (tid + t * 128) * 4;
        *reinterpret_cast<float4*>(Gr + e) = *reinterpret_cast<const float4*>(g_G + b * 2048 + e);
        *reinterpret_cast<float4*>(Gi + e) = *reinterpret_cast<const float4*>(g_G + b * 2048 + 1024 + e);
    }
    __syncthreads();

    unsigned long long acc[8][4];
#pragma unroll
    for (int j = 0; j < 8; j++)
#pragma unroll
        for (int c = 0; c < 4; c++) acc[j][c] = 0ULL;

    // pointwise conv: K = 64 channels
#pragma unroll 16
    for (int i = 0; i < 64; i++) {
        const unsigned long long* hp =
            reinterpret_cast<const unsigned long long*>(hs + i * 132 + nt * 8);
        unsigned long long h0 = hp[0], h1 = hp[1], h2 = hp[2], h3 = hp[3];
#pragma unroll
        for (int j = 0; j < 8; j++) {
            unsigned long long a2 = dup2(Ws[(ot * 8 + j) * 64 + i]);
            acc[j][0] = ff2(a2, h0, acc[j][0]);
            acc[j][1] = ff2(a2, h1, acc[j][1]);
            acc[j][2] = ff2(a2, h2, acc[j][2]);
            acc[j][3] = ff2(a2, h3, acc[j][3]);
        }
    }
    // inverse basis: x1 += Gre*cos - Gim*sin (scales folded into G)
#pragma unroll 4
    for (int k2 = 0; k2 < 16; k2++) {
        const unsigned long long* cp =
            reinterpret_cast<const unsigned long long*>(cs + k2 * 128 + nt * 8);
        const unsigned long long* sp =
            reinterpret_cast<const unsigned long long*>(sn + k2 * 128 + nt * 8);
        unsigned long long c0 = cp[0], c1 = cp[1], c2 = cp[2], c3 = cp[3];
        unsigned long long s0 = sp[0], s1 = sp[1], s2 = sp[2], s3 = sp[3];
#pragma unroll
        for (int j = 0; j < 8; j++) {
            unsigned long long gr2 = dup2(Gr[k2 * 64 + ot * 8 + j]);
            unsigned long long gi2 = dup2(-Gi[k2 * 64 + ot * 8 + j]);
            acc[j][0] = ff2(gr2, c0, acc[j][0]);
            acc[j][1] = ff2(gr2, c1, acc[j][1]);
            acc[j][2] = ff2(gr2, c2, acc[j][2]);
            acc[j][3] = ff2(gr2, c3, acc[j][3]);
            acc[j][0] = ff2(gi2, s0, acc[j][0]);
            acc[j][1] = ff2(gi2, s1, acc[j][1]);
            acc[j][2] = ff2(gi2, s2, acc[j][2]);
            acc[j][3] = ff2(gi2, s3, acc[j][3]);
        }
    }
    // epilogue: bias + exact GELU, store
#pragma unroll
    for (int j = 0; j < 8; j++) {
        int o = ot * 8 + j;
        float bias = __ldg(wb + o);
        float v[8];
#pragma unroll
        for (int c = 0; c < 4; c++) {
            float2 p = unp2(acc[j][c]);
            v[2 * c] = p.x; v[2 * c + 1] = p.y;
        }
#pragma unroll
        for (int c = 0; c < 8; c++) v[c] = gelu_exact(v[c] + bias);
        float4 o0 = make_float4(v[0], v[1], v[2], v[3]);
        float4 o1 = make_float4(v[4], v[5], v[6], v[7]);
        float* dst = out + (size_t)(b * 64 + o) * NPTS + n0 + nt * 8;
        *reinterpret_cast<float4*>(dst) = o0;
        *reinterpret_cast<float4*>(dst + 4) = o1;
    }
}

// ---------------- projection: out[b][n] = sum_w h*qw[w] + qb ----------------
__global__ void k_proj(const float* __restrict__ h, const float* __restrict__ qw,
                       const float* __restrict__ qb, float* __restrict__ out) {
    int idx = blockIdx.x * blockDim.x + threadIdx.x;   // < BATCH*NPTS
    int b = idx >> 13, n = idx & (NPTS - 1);
    float acc = __ldg(qb);
    const float* hp = h + (size_t)b * 64 * NPTS + n;
#pragma unroll 16
    for (int w = 0; w < 64; w++) acc += hp[(size_t)w * NPTS] * __ldg(qw + w);
    out[idx] = acc;
}

// ---------------- launch ----------------
extern "C" void kernel_launch(void* const* d_in, const int* in_sizes, int n_in,
                              void* d_out, int out_size) {
    const float* x  = (const float*)d_in[0];
    const float* pw = (const float*)d_in[1];
    const float* pb = (const float*)d_in[2];
    const float* wr = (const float*)d_in[3];
    const float* wi = (const float*)d_in[4];
    const float* ww = (const float*)d_in[5];
    const float* wb = (const float*)d_in[6];
    const float* qw = (const float*)d_in[7];
    const float* qb = (const float*)d_in[8];
    float* out = (float*)d_out;

    float *hA, *hB;
    cudaGetSymbolAddress((void**)&hA, g_hA);
    cudaGetSymbolAddress((void**)&hB, g_hB);

    const int smLayer = SM_LAYER_FLOATS * 4;   // 74,752 bytes
    cudaFuncSetAttribute(k_layer, cudaFuncAttributeMaxDynamicSharedMemorySize, smLayer);

    k_basis<<<(MODES * NPTS + 255) / 256, 256>>>();
    k_lift<<<HSIZE / 256, 256>>>(x, pw, pb);

    const float* src = hA;
    float* dst = hB;
    for (int l = 0; l < 4; l++) {
        k_fwd<<<dim3(NROWS / 128, KSPLIT), 128>>>(src);
        k_fred<<<(NROWS * 32) / 256, 256>>>();
        k_mix<<<BATCH, 256>>>(wr + l * 65536, wi + l * 65536);
        k_layer<<<dim3(NPTS / 128, BATCH), 128, smLayer>>>(src, dst, ww + l * 4096, wb + l * 64);
        const float* t = src; src = dst; dst = (float*)t;
    }
    k_proj<<<(BATCH * NPTS) / 256, 256>>>(src, qw, qb, out);
}